// round 4
// baseline (speedup 1.0000x reference)
#include <cuda_runtime.h>
#include <cuda_bf16.h>

// ---------------------------------------------------------------------------
// TensorizedEmbedding: out[t, :] = H[idx/400] (16x16) @ T[idx%400] (16x48)
// where H = core0*core1 head table (80 combos), T = core2*core3 tail table
// (400 combos). Tokens are bucketed by tail index so each block keeps its
// T tile in shared memory; H is pre-splatted to float2{v,v} so the packed
// fma.rn.f32x2 inner loop needs no register repacking.
// 5-kernel graph: build(H,T) -> hist -> scan(+self-reset) -> scatter -> main.
// ---------------------------------------------------------------------------

#define NBUCKET 400
#define NHEAD   80
#define MAXB    32768
#define SPLIT   2          // blocks per bucket (load-balance across SMs)

// scratch (device globals: no allocation allowed; zero-init at load)
__device__ __align__(16) float2 g_Hs[NHEAD * 16 * 16];   // [h][r][i] splatted pairs (160 KB)
__device__ __align__(16) float  g_T [NBUCKET * 16 * 64]; // [u][r][jg*8+jj] padded rows (1.6 MB)
__device__ int g_count [NBUCKET];   // zeroed by scan_kernel after use (and at module load)
__device__ int g_offset[NBUCKET + 1];
__device__ int g_cursor[NBUCKET];
__device__ int g_list  [MAXB];

typedef unsigned long long ull;

#define FMA2(d, a, b) asm("fma.rn.f32x2 %0, %1, %2, %3;" : "=l"(d) : "l"(a), "l"(b), "l"(d))

// ---------------- table builder (fused H + T) -------------------------------
// blocks [0, 80):   H[h][i=a*4+m1][r2] = sum_r1 c0[0,d0,a,r1]*c1[r1,d1,m1,r2]
//                   stored splatted: g_Hs[h*256 + r2*16 + i] = {v, v}
// blocks [80, 480): T[u][r2][j=m2*8+m3] = sum_r3 c2[r2,d2,m2,r3]*c3[r3,d3,m3]
//                   padded: slot (j/6)*8 + (j%6) in 64-wide row (pads never read)
__global__ void build_tables_kernel(const float* __restrict__ c0,
                                    const float* __restrict__ c1,
                                    const float* __restrict__ c2,
                                    const float* __restrict__ c3) {
    if (blockIdx.x < NHEAD) {
        int h = blockIdx.x;
        int d0 = h / 10, d1 = h % 10;
        int tid = threadIdx.x;       // 256 threads
        int i = tid >> 4, r2 = tid & 15;
        int a = i >> 2, m1 = i & 3;
        float v = 0.f;
#pragma unroll
        for (int r1 = 0; r1 < 16; r1++)
            v += c0[(d0 * 4 + a) * 16 + r1] *
                 c1[((r1 * 10 + d1) * 4 + m1) * 16 + r2];
        g_Hs[h * 256 + r2 * 16 + i] = make_float2(v, v);
    } else {
        int u = blockIdx.x - NHEAD;
        int d2 = u / 20, d3 = u % 20;
        for (int e = threadIdx.x; e < 768; e += 256) {
            int r2 = e / 48, j = e % 48;
            int m2 = j >> 3, m3 = j & 7;
            float v = 0.f;
#pragma unroll
            for (int r3 = 0; r3 < 16; r3++)
                v += c2[((r2 * 20 + d2) * 6 + m2) * 16 + r3] *
                     c3[(r3 * 20 + d3) * 8 + m3];
            g_T[u * 1024 + r2 * 64 + (j / 6) * 8 + (j % 6)] = v;
        }
    }
}

// ---------------- prefix kernels -------------------------------------------

__global__ void hist_kernel(const int* __restrict__ x, int B) {
    int t = blockIdx.x * 256 + threadIdx.x;
    if (t < B) atomicAdd(&g_count[x[t] % NBUCKET], 1);
}

// reads g_count, writes exclusive prefix to g_offset/g_cursor, then RESETS
// g_count to 0 so the next kernel_launch call starts clean (replaces a
// separate zeroing kernel; deterministic across graph replays).
__global__ void scan_kernel() {
    __shared__ int s[512];
    int t = threadIdx.x;
    int mine = (t < NBUCKET) ? g_count[t] : 0;
    s[t] = mine;
    __syncthreads();
    for (int off = 1; off < 512; off <<= 1) {
        int v = 0;
        if (t >= off) v = s[t - off];
        __syncthreads();
        if (t >= off) s[t] += v;
        __syncthreads();
    }
    if (t < NBUCKET) {
        int excl = s[t] - mine;
        g_offset[t] = excl;
        g_cursor[t] = excl;
        g_count[t] = 0;                       // self-reset for next call
        if (t == NBUCKET - 1) g_offset[NBUCKET] = s[t];
    }
}

__global__ void scatter_kernel(const int* __restrict__ x, int B) {
    int t = blockIdx.x * 256 + threadIdx.x;
    if (t < B) {
        int idx = x[t];
        int u = idx % NBUCKET;
        int h = idx / NBUCKET;            // = d0*10 + d1, < 80
        int pos = atomicAdd(&g_cursor[u], 1);
        g_list[pos] = (t << 7) | h;
    }
}

// ---------------- main kernel ----------------------------------------------
// SPLIT blocks per bucket (800 blocks total). T tile (16x64 padded, 4 KB)
// staged to SMEM once per block. Each warp handles one token per iteration:
// lane = ig*8+jg owns a 4i x 6j output tile; 16-step rank loop, packed
// f32x2 FMAs. No occupancy cap: 400+ CTAs resident -> single wave.
__global__ void __launch_bounds__(256)
tt_main_kernel(float* __restrict__ out) {
    __shared__ __align__(16) float sT[16 * 64];

    int u    = blockIdx.x / SPLIT;
    int half = blockIdx.x % SPLIT;
    // stage T tile: 1024 floats, 256 threads, one float4 each
    ((float4*)sT)[threadIdx.x] = ((const float4*)g_T)[u * 256 + threadIdx.x];
    __syncthreads();

    int start = g_offset[u];
    int end   = g_offset[u + 1];

    int wid  = threadIdx.x >> 5;
    int lane = threadIdx.x & 31;
    int ig = lane >> 3;     // 0..3  -> i rows ig*4 .. ig*4+3
    int jg = lane & 7;      // 0..7  -> j cols jg*6 .. jg*6+5
    const float* tbase = sT + jg * 8;

    for (int p = start + half * 8 + wid; p < end; p += 8 * SPLIT) {
        int packed = g_list[p];
        int t = packed >> 7;
        int h = packed & 127;

        const float2* __restrict__ hp = g_Hs + (h * 256 + ig * 4);

        ull a00 = 0, a01 = 0, a02 = 0;
        ull a10 = 0, a11 = 0, a12 = 0;
        ull a20 = 0, a21 = 0, a22 = 0;
        ull a30 = 0, a31 = 0, a32 = 0;

#pragma unroll
        for (int r = 0; r < 16; r++) {
            const float2* hr = hp + r * 16;
            ulonglong2 hA = *(const ulonglong2*)(hr);       // splat(i0), splat(i1)
            ulonglong2 hB = *(const ulonglong2*)(hr + 2);   // splat(i2), splat(i3)
            const float* tr = tbase + r * 64;
            ulonglong2 t03 = *(const ulonglong2*)(tr);      // {j0j1, j2j3}
            ull        t45 = *(const ull*)(tr + 4);         // {j4j5}

            FMA2(a00, hA.x, t03.x); FMA2(a01, hA.x, t03.y); FMA2(a02, hA.x, t45);
            FMA2(a10, hA.y, t03.x); FMA2(a11, hA.y, t03.y); FMA2(a12, hA.y, t45);
            FMA2(a20, hB.x, t03.x); FMA2(a21, hB.x, t03.y); FMA2(a22, hB.x, t45);
            FMA2(a30, hB.y, t03.x); FMA2(a31, hB.y, t03.y); FMA2(a32, hB.y, t45);
        }

        // out element (i, j) at flat i*48 + j; lane writes 4 rows x 3 float2
        float* op = out + (size_t)t * 768 + ig * 4 * 48 + jg * 6;
        *(ull*)(op +   0) = a00; *(ull*)(op +   2) = a01; *(ull*)(op +   4) = a02;
        *(ull*)(op +  48) = a10; *(ull*)(op +  50) = a11; *(ull*)(op +  52) = a12;
        *(ull*)(op +  96) = a20; *(ull*)(op +  98) = a21; *(ull*)(op + 100) = a22;
        *(ull*)(op + 144) = a30; *(ull*)(op + 146) = a31; *(ull*)(op + 148) = a32;
    }
}

// ---------------- launch ----------------------------------------------------

extern "C" void kernel_launch(void* const* d_in, const int* in_sizes, int n_in,
                              void* d_out, int out_size) {
    const int*   x  = (const int*)d_in[0];
    const float* c0 = (const float*)d_in[1];
    const float* c1 = (const float*)d_in[2];
    const float* c2 = (const float*)d_in[3];
    const float* c3 = (const float*)d_in[4];
    float* out = (float*)d_out;
    int B = in_sizes[0];   // 32768 tokens

    int nblk = (B + 255) / 256;

    build_tables_kernel<<<NHEAD + NBUCKET, 256>>>(c0, c1, c2, c3);
    hist_kernel<<<nblk, 256>>>(x, B);
    scan_kernel<<<1, 512>>>();
    scatter_kernel<<<nblk, 256>>>(x, B);
    tt_main_kernel<<<NBUCKET * SPLIT, 256>>>(out);
}

// round 7
// speedup vs baseline: 1.0735x; 1.0735x over previous
#include <cuda_runtime.h>
#include <cuda_bf16.h>

// ---------------------------------------------------------------------------
// TensorizedEmbedding: out[t, :] = H[idx/400] (16x16) @ T[idx%400] (16x48)
// H = core0*core1 (80 combos), T = core2*core3 (400 combos). Tokens bucketed
// by tail index u with a DETERMINISTIC 3-phase counting sort (no contended
// global atomics). Main kernel keeps T in SMEM with a conflict-free 96-float
// row stride; H pre-splatted to float2{v,v} for packed fma.rn.f32x2.
// 5-kernel graph: build -> blockhist -> basescan -> scatter -> main.
// ---------------------------------------------------------------------------

#define NBUCKET 400
#define NHEAD   80
#define MAXB    32768
#define HB      1024            // threads per hist/scatter block
#define MAXNB   (MAXB / HB)     // 32 blocks
#define SPLIT   2               // main-kernel blocks per bucket
#define TROW    96              // padded T row stride (floats): jg slot = jg*12

// scratch (device globals: no allocation allowed)
__device__ __align__(16) float2 g_Hs[NHEAD * 16 * 16];     // splatted H (160 KB)
__device__ __align__(16) float  g_T [NBUCKET * 16 * TROW]; // padded T (2.4 MB)
__device__ int g_bh   [MAXNB * NBUCKET];   // per-block histograms
__device__ int g_base [MAXNB * NBUCKET];   // per-(block,bucket) output base
__device__ int g_offset[NBUCKET + 1];
__device__ int g_list [MAXB];

typedef unsigned long long ull;

#define FMA2(d, a, b) asm("fma.rn.f32x2 %0, %1, %2, %3;" : "=l"(d) : "l"(a), "l"(b), "l"(d))

// ---------------- table builder (fused H + T) -------------------------------
__global__ void build_tables_kernel(const float* __restrict__ c0,
                                    const float* __restrict__ c1,
                                    const float* __restrict__ c2,
                                    const float* __restrict__ c3) {
    if (blockIdx.x < NHEAD) {
        int h = blockIdx.x;
        int d0 = h / 10, d1 = h % 10;
        int tid = threadIdx.x;       // 256 threads
        int i = tid >> 4, r2 = tid & 15;
        int a = i >> 2, m1 = i & 3;
        float v = 0.f;
#pragma unroll
        for (int r1 = 0; r1 < 16; r1++)
            v += c0[(d0 * 4 + a) * 16 + r1] *
                 c1[((r1 * 10 + d1) * 4 + m1) * 16 + r2];
        g_Hs[h * 256 + r2 * 16 + i] = make_float2(v, v);
    } else {
        int u = blockIdx.x - NHEAD;
        int d2 = u / 20, d3 = u % 20;
        for (int e = threadIdx.x; e < 768; e += 256) {
            int r2 = e / 48, j = e % 48;
            int m2 = j >> 3, m3 = j & 7;
            float v = 0.f;
#pragma unroll
            for (int r3 = 0; r3 < 16; r3++)
                v += c2[((r2 * 20 + d2) * 6 + m2) * 16 + r3] *
                     c3[(r3 * 20 + d3) * 8 + m3];
            // slot: j-group jg = j/6 at jg*12, element j%6 (pads never read)
            g_T[u * (16 * TROW) + r2 * TROW + (j / 6) * 12 + (j % 6)] = v;
        }
    }
}

// ---------------- phase 1: per-block histogram (smem atomics only) ----------
__global__ void blockhist_kernel(const int* __restrict__ x, int B) {
    __shared__ int hcnt[NBUCKET];
    int tid = threadIdx.x;
    if (tid < NBUCKET) hcnt[tid] = 0;
    __syncthreads();
    int t = blockIdx.x * HB + tid;
    if (t < B) atomicAdd(&hcnt[x[t] % NBUCKET], 1);
    __syncthreads();
    if (tid < NBUCKET) g_bh[blockIdx.x * NBUCKET + tid] = hcnt[tid];
}

// ---------------- phase 2: base scan (one block) ----------------------------
// For each bucket u: local prefix over blocks -> g_base[b][u] (pre-offset),
// bucket totals -> block-wide exclusive scan -> g_offset; then add offset
// back into g_base.
__global__ void basescan_kernel(int nb) {
    __shared__ int s[512];
    int u = threadIdx.x;
    int total = 0;
    if (u < NBUCKET) {
        for (int b = 0; b < nb; b++) {
            g_base[b * NBUCKET + u] = total;
            total += g_bh[b * NBUCKET + u];
        }
    }
    s[u] = (u < NBUCKET) ? total : 0;
    __syncthreads();
    for (int off = 1; off < 512; off <<= 1) {
        int v = 0;
        if (u >= off) v = s[u - off];
        __syncthreads();
        if (u >= off) s[u] += v;
        __syncthreads();
    }
    if (u < NBUCKET) {
        int excl = s[u] - total;
        g_offset[u] = excl;
        if (u == NBUCKET - 1) g_offset[NBUCKET] = s[u];
        for (int b = 0; b < nb; b++)
            g_base[b * NBUCKET + u] += excl;
    }
}

// ---------------- phase 3: scatter (smem cursors, no global atomics) --------
__global__ void scatter_kernel(const int* __restrict__ x, int B) {
    __shared__ int cur[NBUCKET];
    int tid = threadIdx.x;
    if (tid < NBUCKET) cur[tid] = g_base[blockIdx.x * NBUCKET + tid];
    __syncthreads();
    int t = blockIdx.x * HB + tid;
    if (t < B) {
        int idx = x[t];
        int u = idx % NBUCKET;
        int h = idx / NBUCKET;            // = d0*10 + d1, < 80
        int pos = atomicAdd(&cur[u], 1);  // shared-memory atomic: fast
        g_list[pos] = (t << 7) | h;
    }
}

// ---------------- main kernel ----------------------------------------------
// SPLIT blocks per bucket (800 blocks). T tile (16 x TROW, 6 KB) staged to
// SMEM once. Each warp handles one token per iteration: lane = ig*8+jg owns
// a 4i x 6j output tile; 16-step rank loop with packed f32x2 FMAs.
// T row layout: j-group jg at byte offset jg*48 -> LDS.128 base banks
// {0,12,24,4,16,28,8,20}: all 32 banks covered, conflict-free.
__global__ void __launch_bounds__(256)
tt_main_kernel(float* __restrict__ out) {
    __shared__ __align__(16) float sT[16 * TROW];

    int u    = blockIdx.x / SPLIT;
    int half = blockIdx.x % SPLIT;
    // stage T tile: 1536 floats = 384 float4, 256 threads
    {
        const float4* src = (const float4*)(g_T + u * (16 * TROW));
        float4* dst = (float4*)sT;
        dst[threadIdx.x] = src[threadIdx.x];
        int i2 = threadIdx.x + 256;
        if (i2 < 384) dst[i2] = src[i2];
    }
    __syncthreads();

    int start = g_offset[u];
    int end   = g_offset[u + 1];

    int wid  = threadIdx.x >> 5;
    int lane = threadIdx.x & 31;
    int ig = lane >> 3;     // 0..3  -> i rows ig*4 .. ig*4+3
    int jg = lane & 7;      // 0..7  -> j cols jg*6 .. jg*6+5
    const float* tbase = sT + jg * 12;

    for (int p = start + half * 8 + wid; p < end; p += 8 * SPLIT) {
        int packed = g_list[p];
        int t = packed >> 7;
        int h = packed & 127;

        const float2* __restrict__ hp = g_Hs + (h * 256 + ig * 4);

        ull a00 = 0, a01 = 0, a02 = 0;
        ull a10 = 0, a11 = 0, a12 = 0;
        ull a20 = 0, a21 = 0, a22 = 0;
        ull a30 = 0, a31 = 0, a32 = 0;

#pragma unroll
        for (int r = 0; r < 16; r++) {
            const float2* hr = hp + r * 16;
            ulonglong2 hA = *(const ulonglong2*)(hr);       // splat(i0), splat(i1)
            ulonglong2 hB = *(const ulonglong2*)(hr + 2);   // splat(i2), splat(i3)
            const float* tr = tbase + r * TROW;
            ulonglong2 t03 = *(const ulonglong2*)(tr);      // {j0j1, j2j3}
            ull        t45 = *(const ull*)(tr + 4);         // {j4j5}

            FMA2(a00, hA.x, t03.x); FMA2(a01, hA.x, t03.y); FMA2(a02, hA.x, t45);
            FMA2(a10, hA.y, t03.x); FMA2(a11, hA.y, t03.y); FMA2(a12, hA.y, t45);
            FMA2(a20, hB.x, t03.x); FMA2(a21, hB.x, t03.y); FMA2(a22, hB.x, t45);
            FMA2(a30, hB.y, t03.x); FMA2(a31, hB.y, t03.y); FMA2(a32, hB.y, t45);
        }

        // out element (i, j) at flat i*48 + j; lane writes 4 rows x 3 float2
        float* op = out + (size_t)t * 768 + ig * 4 * 48 + jg * 6;
        *(ull*)(op +   0) = a00; *(ull*)(op +   2) = a01; *(ull*)(op +   4) = a02;
        *(ull*)(op +  48) = a10; *(ull*)(op +  50) = a11; *(ull*)(op +  52) = a12;
        *(ull*)(op +  96) = a20; *(ull*)(op +  98) = a21; *(ull*)(op + 100) = a22;
        *(ull*)(op + 144) = a30; *(ull*)(op + 146) = a31; *(ull*)(op + 148) = a32;
    }
}

// ---------------- launch ----------------------------------------------------

extern "C" void kernel_launch(void* const* d_in, const int* in_sizes, int n_in,
                              void* d_out, int out_size) {
    const int*   x  = (const int*)d_in[0];
    const float* c0 = (const float*)d_in[1];
    const float* c1 = (const float*)d_in[2];
    const float* c2 = (const float*)d_in[3];
    const float* c3 = (const float*)d_in[4];
    float* out = (float*)d_out;
    int B = in_sizes[0];   // 32768 tokens

    int nb = (B + HB - 1) / HB;   // 32 hist/scatter blocks

    build_tables_kernel<<<NHEAD + NBUCKET, 256>>>(c0, c1, c2, c3);
    blockhist_kernel<<<nb, HB>>>(x, B);
    basescan_kernel<<<1, 512>>>(nb);
    scatter_kernel<<<nb, HB>>>(x, B);
    tt_main_kernel<<<NBUCKET * SPLIT, 256>>>(out);
}

// round 9
// speedup vs baseline: 1.4435x; 1.3446x over previous
#include <cuda_runtime.h>
#include <cuda_bf16.h>

// ---------------------------------------------------------------------------
// TensorizedEmbedding: out[t, :] = H[idx/400] (16x16) @ T[idx%400] (16x48)
// r-paired FFMA2 formulation: accumulators hold {even-r partial, odd-r partial}
// so BOTH operands are natural 64-bit pairs (no splat tables, half the H LDGs).
// H: g_Hp[h][k][i][{2k,2k+1}] pairs; T: transposed [j][r] in SMEM (TROWT=18,
// bank-conflict-free LDS.64). Deterministic counting sort, 6-kernel graph.
// ---------------------------------------------------------------------------

#define NBUCKET 400
#define NHEAD   80
#define MAXB    32768
#define HB      256             // tokens per hist/scatter block
#define MAXNB   (MAXB / HB)     // 128 blocks
#define TROWT   18              // padded transposed-T row stride (floats)

// scratch (device globals: no allocation allowed)
__device__ __align__(16) float g_Hp[NHEAD * 256];          // [h][k][i][2] pairs (80 KB)
__device__ __align__(16) float g_Tt[NBUCKET * 48 * 16];    // [u][j][r] transposed (1.2 MB)
__device__ int g_bh  [NBUCKET * MAXNB];   // [u][b] per-block histograms
__device__ int g_base[NBUCKET * MAXNB];   // [u][b] per-(bucket,block) base
__device__ int g_tot [NBUCKET];
__device__ int g_offset[NBUCKET + 1];
__device__ int g_list[MAXB];

typedef unsigned long long ull;

#define FMA2(d, a, b) asm("fma.rn.f32x2 %0, %1, %2, %3;" : "=l"(d) : "l"(a), "l"(b), "l"(d))

static __device__ __forceinline__ float hsum2(ull v) {
    float lo = __int_as_float((int)(v & 0xffffffffu));
    float hi = __int_as_float((int)(v >> 32));
    return lo + hi;
}

// ---------------- table builder (fused H + T) -------------------------------
// blocks [0,80):   H[h][i][r2] = sum_r1 c0[0,d0,a,r1]*c1[r1,d1,m1,r2], i=a*4+m1
//                  stored as r-pairs: g_Hp[h*256 + (r2/2)*32 + i*2 + (r2&1)]
// blocks [80,480): T[u][r2][j] = sum_r3 c2[r2,d2,m2,r3]*c3[r3,d3,m3], j=m2*8+m3
//                  stored transposed: g_Tt[u*768 + j*16 + r2]
__global__ void build_tables_kernel(const float* __restrict__ c0,
                                    const float* __restrict__ c1,
                                    const float* __restrict__ c2,
                                    const float* __restrict__ c3) {
    if (blockIdx.x < NHEAD) {
        int h = blockIdx.x;
        int d0 = h / 10, d1 = h % 10;
        int tid = threadIdx.x;       // 256 threads
        int i = tid >> 4, r2 = tid & 15;
        int a = i >> 2, m1 = i & 3;
        float v = 0.f;
#pragma unroll
        for (int r1 = 0; r1 < 16; r1++)
            v += c0[(d0 * 4 + a) * 16 + r1] *
                 c1[((r1 * 10 + d1) * 4 + m1) * 16 + r2];
        g_Hp[h * 256 + (r2 >> 1) * 32 + i * 2 + (r2 & 1)] = v;
    } else {
        int u = blockIdx.x - NHEAD;
        int d2 = u / 20, d3 = u % 20;
        for (int e = threadIdx.x; e < 768; e += 256) {
            int r2 = e / 48, j = e % 48;
            int m2 = j >> 3, m3 = j & 7;
            float v = 0.f;
#pragma unroll
            for (int r3 = 0; r3 < 16; r3++)
                v += c2[((r2 * 20 + d2) * 6 + m2) * 16 + r3] *
                     c3[(r3 * 20 + d3) * 8 + m3];
            g_Tt[u * 768 + j * 16 + r2] = v;
        }
    }
}

// ---------------- phase 1: per-block histogram ------------------------------
__global__ void blockhist_kernel(const int* __restrict__ x, int B) {
    __shared__ int hcnt[NBUCKET];
    int tid = threadIdx.x;
    for (int i = tid; i < NBUCKET; i += HB) hcnt[i] = 0;
    __syncthreads();
    int t = blockIdx.x * HB + tid;
    if (t < B) atomicAdd(&hcnt[x[t] % NBUCKET], 1);
    __syncthreads();
    for (int i = tid; i < NBUCKET; i += HB)
        g_bh[i * MAXNB + blockIdx.x] = hcnt[i];
}

// ---------------- phase 2a: per-bucket column scan (warp per bucket) --------
// g_base[u][b] = sum_{b'<b} g_bh[u][b'];  g_tot[u] = total count for u.
__global__ void colscan_kernel() {
    int w = (blockIdx.x * blockDim.x + threadIdx.x) >> 5;
    int l = threadIdx.x & 31;
    if (w >= NBUCKET) return;
    int4 v = ((const int4*)(g_bh + w * MAXNB))[l];   // b = 4l .. 4l+3
    int p1 = v.x, p2 = p1 + v.y, p3 = p2 + v.z, tot = p3 + v.w;
    int inc = tot;
#pragma unroll
    for (int off = 1; off < 32; off <<= 1) {
        int n = __shfl_up_sync(0xffffffffu, inc, off);
        if (l >= off) inc += n;
    }
    int excl = inc - tot;
    ((int4*)(g_base + w * MAXNB))[l] = make_int4(excl, excl + p1, excl + p2, excl + p3);
    if (l == 31) g_tot[w] = inc;
}

// ---------------- phase 2b: bucket-offset scan (one block) ------------------
__global__ void offsetscan_kernel() {
    __shared__ int s[512];
    int u = threadIdx.x;
    int mine = (u < NBUCKET) ? g_tot[u] : 0;
    s[u] = mine;
    __syncthreads();
    for (int off = 1; off < 512; off <<= 1) {
        int v = 0;
        if (u >= off) v = s[u - off];
        __syncthreads();
        if (u >= off) s[u] += v;
        __syncthreads();
    }
    if (u < NBUCKET) {
        g_offset[u] = s[u] - mine;
        if (u == NBUCKET - 1) g_offset[NBUCKET] = s[u];
    }
}

// ---------------- phase 3: scatter (smem cursors) ---------------------------
__global__ void scatter_kernel(const int* __restrict__ x, int B) {
    __shared__ int cur[NBUCKET];
    int tid = threadIdx.x;
    for (int i = tid; i < NBUCKET; i += HB)
        cur[i] = g_offset[i] + g_base[i * MAXNB + blockIdx.x];
    __syncthreads();
    int t = blockIdx.x * HB + tid;
    if (t < B) {
        int idx = x[t];
        int u = idx % NBUCKET;
        int h = idx / NBUCKET;            // = d0*10 + d1, < 80
        int pos = atomicAdd(&cur[u], 1);
        g_list[pos] = (t << 7) | h;
    }
}

// ---------------- main kernel ----------------------------------------------
// One 128-thread block per bucket (400 blocks, single wave at occ>=3).
// Transposed T tile (48 x TROWT, 3.5 KB) staged to SMEM once. Each warp
// handles one token per iteration; lane = ig*8+jg owns a 4i x 6j tile.
// r-paired: 8 k-steps; per k: 2 LDG.128 (H pairs) + 6 LDS.64 (T pairs,
// conflict-free: jg*6*18 mod 32 words all distinct) + 24 FFMA2.
__global__ void __launch_bounds__(128, 3)
tt_main_kernel(float* __restrict__ out) {
    __shared__ __align__(16) float sTt[48 * TROWT];

    int u = blockIdx.x;
    // stage transposed T tile with pad: 768 floats, 128 threads
    for (int e = threadIdx.x; e < 768; e += 128) {
        int j = e >> 4, r = e & 15;
        sTt[j * TROWT + r] = g_Tt[u * 768 + e];
    }
    __syncthreads();

    int start = g_offset[u];
    int end   = g_offset[u + 1];

    int wid  = threadIdx.x >> 5;     // 0..3
    int lane = threadIdx.x & 31;
    int ig = lane >> 3;              // 0..3 -> i rows ig*4 .. ig*4+3
    int jg = lane & 7;               // 0..7 -> j cols jg*6 .. jg*6+5
    const float* tb = sTt + jg * 6 * TROWT;

    for (int p = start + wid; p < end; p += 4) {
        int packed = g_list[p];
        int t = packed >> 7;
        int h = packed & 127;

        const float* hbase = g_Hp + h * 256 + ig * 8;   // + k*32 per step

        ull a00 = 0, a01 = 0, a02 = 0, a03 = 0, a04 = 0, a05 = 0;
        ull a10 = 0, a11 = 0, a12 = 0, a13 = 0, a14 = 0, a15 = 0;
        ull a20 = 0, a21 = 0, a22 = 0, a23 = 0, a24 = 0, a25 = 0;
        ull a30 = 0, a31 = 0, a32 = 0, a33 = 0, a34 = 0, a35 = 0;

#pragma unroll
        for (int k = 0; k < 8; k++) {
            // H r-pairs for this lane's 4 i-rows: 32 B = 2x LDG.128
            ulonglong2 hA = *(const ulonglong2*)(hbase + k * 32);      // pair(i0), pair(i1)
            ulonglong2 hB = *(const ulonglong2*)(hbase + k * 32 + 4);  // pair(i2), pair(i3)
            // T r-pairs for this lane's 6 j-cols: 6x LDS.64
            const float* tk = tb + 2 * k;
            ull t0 = *(const ull*)(tk);
            ull t1 = *(const ull*)(tk + TROWT);
            ull t2 = *(const ull*)(tk + 2 * TROWT);
            ull t3 = *(const ull*)(tk + 3 * TROWT);
            ull t4 = *(const ull*)(tk + 4 * TROWT);
            ull t5 = *(const ull*)(tk + 5 * TROWT);

            FMA2(a00, hA.x, t0); FMA2(a01, hA.x, t1); FMA2(a02, hA.x, t2);
            FMA2(a03, hA.x, t3); FMA2(a04, hA.x, t4); FMA2(a05, hA.x, t5);
            FMA2(a10, hA.y, t0); FMA2(a11, hA.y, t1); FMA2(a12, hA.y, t2);
            FMA2(a13, hA.y, t3); FMA2(a14, hA.y, t4); FMA2(a15, hA.y, t5);
            FMA2(a20, hB.x, t0); FMA2(a21, hB.x, t1); FMA2(a22, hB.x, t2);
            FMA2(a23, hB.x, t3); FMA2(a24, hB.x, t4); FMA2(a25, hB.x, t5);
            FMA2(a30, hB.y, t0); FMA2(a31, hB.y, t1); FMA2(a32, hB.y, t2);
            FMA2(a33, hB.y, t3); FMA2(a34, hB.y, t4); FMA2(a35, hB.y, t5);
        }

        // horizontal add (even-r + odd-r) and store: 4 rows x 3 float2
        float* op = out + (size_t)t * 768 + ig * 4 * 48 + jg * 6;
        *(float2*)(op +   0) = make_float2(hsum2(a00), hsum2(a01));
        *(float2*)(op +   2) = make_float2(hsum2(a02), hsum2(a03));
        *(float2*)(op +   4) = make_float2(hsum2(a04), hsum2(a05));
        *(float2*)(op +  48) = make_float2(hsum2(a10), hsum2(a11));
        *(float2*)(op +  50) = make_float2(hsum2(a12), hsum2(a13));
        *(float2*)(op +  52) = make_float2(hsum2(a14), hsum2(a15));
        *(float2*)(op +  96) = make_float2(hsum2(a20), hsum2(a21));
        *(float2*)(op +  98) = make_float2(hsum2(a22), hsum2(a23));
        *(float2*)(op + 100) = make_float2(hsum2(a24), hsum2(a25));
        *(float2*)(op + 144) = make_float2(hsum2(a30), hsum2(a31));
        *(float2*)(op + 146) = make_float2(hsum2(a32), hsum2(a33));
        *(float2*)(op + 148) = make_float2(hsum2(a34), hsum2(a35));
    }
}

// ---------------- launch ----------------------------------------------------

extern "C" void kernel_launch(void* const* d_in, const int* in_sizes, int n_in,
                              void* d_out, int out_size) {
    const int*   x  = (const int*)d_in[0];
    const float* c0 = (const float*)d_in[1];
    const float* c1 = (const float*)d_in[2];
    const float* c2 = (const float*)d_in[3];
    const float* c3 = (const float*)d_in[4];
    float* out = (float*)d_out;
    int B = in_sizes[0];   // 32768 tokens

    int nb = (B + HB - 1) / HB;                 // 128
    int cs_blocks = (NBUCKET * 32 + 511) / 512; // 25

    build_tables_kernel<<<NHEAD + NBUCKET, 256>>>(c0, c1, c2, c3);
    blockhist_kernel<<<nb, HB>>>(x, B);
    colscan_kernel<<<cs_blocks, 512>>>();
    offsetscan_kernel<<<1, 512>>>();
    scatter_kernel<<<nb, HB>>>(x, B);
    tt_main_kernel<<<NBUCKET, 128>>>(out);
}